// round 7
// baseline (speedup 1.0000x reference)
#include <cuda_runtime.h>
#include <cuda_fp16.h>
#include <cstdint>

// ---------------------------------------------------------------------------
// KANClassifier fp16 mma.sync. Round 7: 512-thread GEMM CTAs (16 warps,
// 4 warps/SMSP) to fill HMMA issue gaps; warp tile 32x64; single-buffered
// fragments (RF bound 128 regs/thread).
// ---------------------------------------------------------------------------

#define BATCH   4096
#define IN_DIM  1024
#define KDIM    16384
#define HIDDEN  4096
#define CLASSES 1000
#define NPAD    1024

#define KT1 (KDIM / 32)
#define KT2 (HIDDEN / 32)

__device__ __align__(1024) uint4 g_F  [(size_t)BATCH * KDIM / 8];
__device__ __align__(1024) uint4 g_PHI[(size_t)BATCH * HIDDEN / 8];
__device__ __align__(1024) uint4 g_WbP[(size_t)KDIM * HIDDEN / 8];
__device__ __align__(1024) uint4 g_WhP[(size_t)HIDDEN * NPAD / 8];

__device__ __forceinline__ uint32_t pack_half2(float a, float b) {
    __half2 h = __floats2half2_rn(a, b);
    return *reinterpret_cast<uint32_t*>(&h);
}
__device__ __forceinline__ float mufu_tanh(float v) {
    float r;
    asm("tanh.approx.f32 %0, %1;" : "=f"(r) : "f"(v));
    return r;
}
__device__ __forceinline__ void cp_async16(uint32_t saddr, const void* gptr) {
    asm volatile("cp.async.cg.shared.global [%0], [%1], 16;\n" :: "r"(saddr), "l"(gptr));
}

// ---------------------------------------------------------------------------
// Kernel 1: tanh basis -> g_F packed fp16 (A fragment layout)
// ---------------------------------------------------------------------------
__global__ void feats_packed_kernel(const float* __restrict__ x,
                                    const float* __restrict__ centers,
                                    const float* __restrict__ scales,
                                    uint4* __restrict__ F) {
    int g = blockIdx.x * blockDim.x + threadIdx.x;
    int lane = g & 31, grp = (g >> 5) & 7, ks = (g >> 8) & 1;
    int kt = (g >> 9) & (KT1 - 1), mt = g >> 18;
    int rlo = lane >> 2, klane = lane & 3;
    int r = mt * 128 + grp * 16 + rlo;
    int d = kt * 2 + ks;
    int j0 = klane * 2;

    float xv0 = __ldg(x + (size_t)r * IN_DIM + d);
    float xv1 = __ldg(x + (size_t)(r + 8) * IN_DIM + d);
    const float* cd = centers + d * 16;
    const float* sd = scales + d * 16;
    float c0 = __ldg(cd + j0), c1 = __ldg(cd + j0 + 1);
    float c8 = __ldg(cd + j0 + 8), c9 = __ldg(cd + j0 + 9);
    float s0 = __ldg(sd + j0), s1 = __ldg(sd + j0 + 1);
    float s8 = __ldg(sd + j0 + 8), s9 = __ldg(sd + j0 + 9);

    uint4 o;
    o.x = pack_half2(mufu_tanh((xv0 - c0) * s0), mufu_tanh((xv0 - c1) * s1));
    o.y = pack_half2(mufu_tanh((xv1 - c0) * s0), mufu_tanh((xv1 - c1) * s1));
    o.z = pack_half2(mufu_tanh((xv0 - c8) * s8), mufu_tanh((xv0 - c9) * s9));
    o.w = pack_half2(mufu_tanh((xv1 - c8) * s8), mufu_tanh((xv1 - c9) * s9));
    F[g] = o;
}

// Kernel 2: fp32 W [K][Nsrc] -> packed fp16 B-layout (pad cols >= Nsrc)
__global__ void convert_pack_b_kernel(const float* __restrict__ W,
                                      uint4* __restrict__ out,
                                      int KT, int Nsrc) {
    int g = blockIdx.x * blockDim.x + threadIdx.x;
    int lane = g & 31, npair = (g >> 5) & 15, ks = (g >> 9) & 1;
    int tile = g >> 10;
    int kt = tile % KT, nt = tile / KT;
    int k0 = kt * 32 + ks * 16 + (lane & 3) * 2;
    int c  = nt * 256 + npair * 16 + (lane >> 2);
    int c8 = c + 8;

    const float* w0 = W + (size_t)k0 * Nsrc;
    float a00 = 0.f, a10 = 0.f, a80 = 0.f, a90 = 0.f;
    float a08 = 0.f, a18 = 0.f, a88 = 0.f, a98 = 0.f;
    if (c < Nsrc) {
        a00 = __ldg(w0 + c);
        a10 = __ldg(w0 + Nsrc + c);
        a80 = __ldg(w0 + (size_t)8 * Nsrc + c);
        a90 = __ldg(w0 + (size_t)9 * Nsrc + c);
    }
    if (c8 < Nsrc) {
        a08 = __ldg(w0 + c8);
        a18 = __ldg(w0 + Nsrc + c8);
        a88 = __ldg(w0 + (size_t)8 * Nsrc + c8);
        a98 = __ldg(w0 + (size_t)9 * Nsrc + c8);
    }
    uint4 o;
    o.x = pack_half2(a00, a10);
    o.y = pack_half2(a80, a90);
    o.z = pack_half2(a08, a18);
    o.w = pack_half2(a88, a98);
    out[g] = o;
}

// ---------------------------------------------------------------------------
// fp16 GEMM: 128x256 block, BK=64, 4 stages (192KB), 16 warps (4M x 4N),
// warp tile 32x64. 512 threads, <=128 regs/thread.
// ---------------------------------------------------------------------------
#define STAGES 4
#define A_CH 1024
#define B_CH 2048
#define SMEM_BYTES (STAGES * (A_CH + B_CH) * 16)   // 192KB

__device__ __forceinline__ void mma16816(float* d, const uint4& a,
                                         uint32_t b0, uint32_t b1) {
    asm volatile(
        "mma.sync.aligned.m16n8k16.row.col.f32.f16.f16.f32 "
        "{%0,%1,%2,%3}, {%4,%5,%6,%7}, {%8,%9}, {%0,%1,%2,%3};\n"
        : "+f"(d[0]), "+f"(d[1]), "+f"(d[2]), "+f"(d[3])
        : "r"(a.x), "r"(a.y), "r"(a.z), "r"(a.w), "r"(b0), "r"(b1));
}

template <bool SIGMOID, bool PACKED_OUT>
__global__ void __launch_bounds__(512, 1)
gemm_fp16_kernel(const uint4* __restrict__ Apk,
                 const uint4* __restrict__ Bpk,
                 const float* __restrict__ bias,
                 void* __restrict__ outp,
                 int KTs, int KTout, int Nreal, int nTiles) {
    extern __shared__ uint4 sm4[];
    uint4* As = sm4;
    uint4* Bs = sm4 + STAGES * A_CH;

    const int tid = threadIdx.x;
    const int lane = tid & 31;
    const int warp = tid >> 5;
    const int wm = warp & 3, wn = warp >> 2;   // 4M x 4N
    const int lr = lane >> 2, lc = lane & 3;

    const int GRP = 8;
    int per = GRP * nTiles;
    int mt = (blockIdx.x / per) * GRP + (blockIdx.x % per) % GRP;
    int nt = (blockIdx.x % per) / GRP;
    const int m0 = mt * 128, n0 = nt * 256;
    const int KT2c = KTs / 2;

    float acc[2][8][4];
#pragma unroll
    for (int i = 0; i < 2; i++)
#pragma unroll
        for (int j = 0; j < 8; j++)
#pragma unroll
            for (int k = 0; k < 4; k++) acc[i][j][k] = 0.f;

    auto load_stage = [&](int kt2, int s) {
        const uint4* ag = Apk + ((size_t)mt * KTs + kt2 * 2) * 512;
        uint4* as = As + s * A_CH;
#pragma unroll
        for (int p = 0; p < 2; p++) {
            int ci = tid + p * 512;
            cp_async16((uint32_t)__cvta_generic_to_shared(as + ci), ag + ci);
        }
        const uint4* bg = Bpk + ((size_t)nt * KTs + kt2 * 2) * 1024;
        uint4* bs = Bs + s * B_CH;
#pragma unroll
        for (int p = 0; p < 4; p++) {
            int ci = tid + p * 512;
            cp_async16((uint32_t)__cvta_generic_to_shared(bs + ci), bg + ci);
        }
        asm volatile("cp.async.commit_group;\n");
    };

    load_stage(0, 0);
    load_stage(1, 1);
    load_stage(2, 2);

    for (int kt2 = 0; kt2 < KT2c; kt2++) {
        asm volatile("cp.async.wait_group 2;\n");
        __syncthreads();
        if (kt2 + 3 < KT2c) load_stage(kt2 + 3, (kt2 + 3) & (STAGES - 1));
        else asm volatile("cp.async.commit_group;\n");

        const int s = kt2 & (STAGES - 1);
        const uint4* as = As + s * A_CH;
        const uint4* bs = Bs + s * B_CH;

#pragma unroll
        for (int ksg = 0; ksg < 4; ksg++) {
            const int half = ksg >> 1, ks = ksg & 1;
            uint4 av[2];
#pragma unroll
            for (int mf = 0; mf < 2; mf++)
                av[mf] = as[half * 512 + ks * 256 + (wm * 2 + mf) * 32 + lane];
            uint4 bv[4];
#pragma unroll
            for (int np = 0; np < 4; np++)
                bv[np] = bs[half * 1024 + (ks * 16 + wn * 4 + np) * 32 + lane];
#pragma unroll
            for (int mf = 0; mf < 2; mf++)
#pragma unroll
                for (int np = 0; np < 4; np++) {
                    mma16816(acc[mf][2 * np],     av[mf], bv[np].x, bv[np].y);
                    mma16816(acc[mf][2 * np + 1], av[mf], bv[np].z, bv[np].w);
                }
        }
        // next iteration's top barrier orders stage reuse
    }

    // ------------------ epilogue ------------------
#pragma unroll
    for (int mf = 0; mf < 2; mf++) {
        const int r0 = m0 + wm * 32 + mf * 16 + lr;
        const int grp = wm * 2 + mf;
#pragma unroll
        for (int npi = 0; npi < 4; npi++) {
            const int nf = npi * 2;
            const int c = n0 + wn * 64 + nf * 8 + lc * 2;
            float b0 = 0.f, b1 = 0.f, b2 = 0.f, b3 = 0.f;
            if (!PACKED_OUT) {
                if (c < Nreal)     b0 = __ldg(bias + c);
                if (c + 1 < Nreal) b1 = __ldg(bias + c + 1);
                if (c + 8 < Nreal) b2 = __ldg(bias + c + 8);
                if (c + 9 < Nreal) b3 = __ldg(bias + c + 9);
            } else {
                b0 = __ldg(bias + c);     b1 = __ldg(bias + c + 1);
                b2 = __ldg(bias + c + 8); b3 = __ldg(bias + c + 9);
            }
            float v00 = acc[mf][nf][0] + b0,     v01 = acc[mf][nf][1] + b1;
            float v10 = acc[mf][nf][2] + b0,     v11 = acc[mf][nf][3] + b1;
            float v20 = acc[mf][nf + 1][0] + b2, v21 = acc[mf][nf + 1][1] + b3;
            float v30 = acc[mf][nf + 1][2] + b2, v31 = acc[mf][nf + 1][3] + b3;
            if (SIGMOID) {
                v00 = 1.f / (1.f + __expf(-v00)); v01 = 1.f / (1.f + __expf(-v01));
                v10 = 1.f / (1.f + __expf(-v10)); v11 = 1.f / (1.f + __expf(-v11));
                v20 = 1.f / (1.f + __expf(-v20)); v21 = 1.f / (1.f + __expf(-v21));
                v30 = 1.f / (1.f + __expf(-v30)); v31 = 1.f / (1.f + __expf(-v31));
            }
            if (PACKED_OUT) {
                int kt2o = c >> 5;
                int ks2 = npi & 1;
                size_t chunk = ((size_t)mt * KTout + kt2o) * 512
                             + ks2 * 256 + grp * 32 + lane;
                uint4 o;
                o.x = pack_half2(v00, v01);
                o.y = pack_half2(v10, v11);
                o.z = pack_half2(v20, v21);
                o.w = pack_half2(v30, v31);
                reinterpret_cast<uint4*>(outp)[chunk] = o;
            } else {
                float* C = reinterpret_cast<float*>(outp);
                if (c < Nreal)     C[(size_t)r0 * Nreal + c] = v00;
                if (c + 1 < Nreal) C[(size_t)r0 * Nreal + c + 1] = v01;
                if (c < Nreal)     C[(size_t)(r0 + 8) * Nreal + c] = v10;
                if (c + 1 < Nreal) C[(size_t)(r0 + 8) * Nreal + c + 1] = v11;
                if (c + 8 < Nreal) C[(size_t)r0 * Nreal + c + 8] = v20;
                if (c + 9 < Nreal) C[(size_t)r0 * Nreal + c + 9] = v21;
                if (c + 8 < Nreal) C[(size_t)(r0 + 8) * Nreal + c + 8] = v30;
                if (c + 9 < Nreal) C[(size_t)(r0 + 8) * Nreal + c + 9] = v31;
            }
        }
    }
}

// ---------------------------------------------------------------------------
// Launch
// ---------------------------------------------------------------------------
extern "C" void kernel_launch(void* const* d_in, const int* in_sizes, int n_in,
                              void* d_out, int out_size) {
    const float* x       = (const float*)d_in[0];
    const float* centers = (const float*)d_in[1];
    const float* scales  = (const float*)d_in[2];
    const float* Wb      = (const float*)d_in[3];
    const float* bb      = (const float*)d_in[4];
    const float* Wh      = (const float*)d_in[5];
    const float* bh      = (const float*)d_in[6];
    float* out = (float*)d_out;

    uint4 *F, *PHI, *WbP, *WhP;
    cudaGetSymbolAddress((void**)&F, g_F);
    cudaGetSymbolAddress((void**)&PHI, g_PHI);
    cudaGetSymbolAddress((void**)&WbP, g_WbP);
    cudaGetSymbolAddress((void**)&WhP, g_WhP);

    cudaFuncSetAttribute((const void*)gemm_fp16_kernel<true, true>,
                         cudaFuncAttributeMaxDynamicSharedMemorySize, SMEM_BYTES);
    cudaFuncSetAttribute((const void*)gemm_fp16_kernel<false, false>,
                         cudaFuncAttributeMaxDynamicSharedMemorySize, SMEM_BYTES);

    // 1) feats -> packed fp16 F
    {
        size_t chunks = (size_t)BATCH * KDIM / 8;
        feats_packed_kernel<<<(int)(chunks / 256), 256>>>(x, centers, scales, F);
    }
    // 2) pack Wb, Wh
    {
        size_t cb = (size_t)KDIM * HIDDEN / 8;
        convert_pack_b_kernel<<<(int)(cb / 256), 256>>>(Wb, WbP, KT1, HIDDEN);
        size_t ch = (size_t)HIDDEN * NPAD / 8;
        convert_pack_b_kernel<<<(int)(ch / 256), 256>>>(Wh, WhP, KT2, CLASSES);
    }
    // 3) GEMM1: PHI(packed) = sigmoid(F @ Wb + bb)
    {
        int nT = HIDDEN / 256;
        int grid = (BATCH / 128) * nT;
        gemm_fp16_kernel<true, true><<<grid, 512, SMEM_BYTES>>>(
            F, WbP, bb, PHI, KT1, KT2, HIDDEN, nT);
    }
    // 4) GEMM2: out = PHI @ Wh + bh
    {
        int nT = NPAD / 256;
        int grid = (BATCH / 128) * nT;
        gemm_fp16_kernel<false, false><<<grid, 512, SMEM_BYTES>>>(
            PHI, WhP, bh, out, KT2, 0, CLASSES, nT);
    }
}

// round 8
// speedup vs baseline: 1.1724x; 1.1724x over previous
#include <cuda_runtime.h>
#include <cuda_fp16.h>
#include <cstdint>

// ---------------------------------------------------------------------------
// KANClassifier fp16 mma.sync. Round 8: 128x128x64 tiles, 3-stage 96KB smem,
// 2 CTAs/SM (independent barriers keep HMMA pipe fed), 8 warps (2M x 4N).
// ---------------------------------------------------------------------------

#define BATCH   4096
#define IN_DIM  1024
#define KDIM    16384
#define HIDDEN  4096
#define CLASSES 1000
#define NPAD    1024

#define KT1 (KDIM / 32)
#define KT2 (HIDDEN / 32)

__device__ __align__(1024) uint4 g_F  [(size_t)BATCH * KDIM / 8];
__device__ __align__(1024) uint4 g_PHI[(size_t)BATCH * HIDDEN / 8];
__device__ __align__(1024) uint4 g_WbP[(size_t)KDIM * HIDDEN / 8];
__device__ __align__(1024) uint4 g_WhP[(size_t)HIDDEN * NPAD / 8];

__device__ __forceinline__ uint32_t pack_half2(float a, float b) {
    __half2 h = __floats2half2_rn(a, b);
    return *reinterpret_cast<uint32_t*>(&h);
}
__device__ __forceinline__ float mufu_tanh(float v) {
    float r;
    asm("tanh.approx.f32 %0, %1;" : "=f"(r) : "f"(v));
    return r;
}
__device__ __forceinline__ void cp_async16(uint32_t saddr, const void* gptr) {
    asm volatile("cp.async.cg.shared.global [%0], [%1], 16;\n" :: "r"(saddr), "l"(gptr));
}

// ---------------------------------------------------------------------------
// Kernel 1: tanh basis -> g_F packed fp16 (A fragment layout, 128r x 32k tiles)
// ---------------------------------------------------------------------------
__global__ void feats_packed_kernel(const float* __restrict__ x,
                                    const float* __restrict__ centers,
                                    const float* __restrict__ scales,
                                    uint4* __restrict__ F) {
    int g = blockIdx.x * blockDim.x + threadIdx.x;
    int lane = g & 31, grp = (g >> 5) & 7, ks = (g >> 8) & 1;
    int kt = (g >> 9) & (KT1 - 1), mt = g >> 18;
    int rlo = lane >> 2, klane = lane & 3;
    int r = mt * 128 + grp * 16 + rlo;
    int d = kt * 2 + ks;
    int j0 = klane * 2;

    float xv0 = __ldg(x + (size_t)r * IN_DIM + d);
    float xv1 = __ldg(x + (size_t)(r + 8) * IN_DIM + d);
    const float* cd = centers + d * 16;
    const float* sd = scales + d * 16;
    float c0 = __ldg(cd + j0), c1 = __ldg(cd + j0 + 1);
    float c8 = __ldg(cd + j0 + 8), c9 = __ldg(cd + j0 + 9);
    float s0 = __ldg(sd + j0), s1 = __ldg(sd + j0 + 1);
    float s8 = __ldg(sd + j0 + 8), s9 = __ldg(sd + j0 + 9);

    uint4 o;
    o.x = pack_half2(mufu_tanh((xv0 - c0) * s0), mufu_tanh((xv0 - c1) * s1));
    o.y = pack_half2(mufu_tanh((xv1 - c0) * s0), mufu_tanh((xv1 - c1) * s1));
    o.z = pack_half2(mufu_tanh((xv0 - c8) * s8), mufu_tanh((xv0 - c9) * s9));
    o.w = pack_half2(mufu_tanh((xv1 - c8) * s8), mufu_tanh((xv1 - c9) * s9));
    F[g] = o;
}

// ---------------------------------------------------------------------------
// Kernel 2: fp32 W [K][Nsrc] -> packed fp16 B-layout, 32k x 128n tiles
// (512 chunks/tile). chunk = (ks*8 + npair)*32 + lane
//   k0 = kt*32 + ks*16 + (lane&3)*2, c = nt*128 + npair*16 + (lane>>2)
// ---------------------------------------------------------------------------
__global__ void convert_pack_b_kernel(const float* __restrict__ W,
                                      uint4* __restrict__ out,
                                      int KT, int Nsrc) {
    int g = blockIdx.x * blockDim.x + threadIdx.x;
    int lane = g & 31, npair = (g >> 5) & 7, ks = (g >> 8) & 1;
    int tile = g >> 9;
    int kt = tile % KT, nt = tile / KT;
    int k0 = kt * 32 + ks * 16 + (lane & 3) * 2;
    int c  = nt * 128 + npair * 16 + (lane >> 2);
    int c8 = c + 8;

    const float* w0 = W + (size_t)k0 * Nsrc;
    float a00 = 0.f, a10 = 0.f, a80 = 0.f, a90 = 0.f;
    float a08 = 0.f, a18 = 0.f, a88 = 0.f, a98 = 0.f;
    if (c < Nsrc) {
        a00 = __ldg(w0 + c);
        a10 = __ldg(w0 + Nsrc + c);
        a80 = __ldg(w0 + (size_t)8 * Nsrc + c);
        a90 = __ldg(w0 + (size_t)9 * Nsrc + c);
    }
    if (c8 < Nsrc) {
        a08 = __ldg(w0 + c8);
        a18 = __ldg(w0 + Nsrc + c8);
        a88 = __ldg(w0 + (size_t)8 * Nsrc + c8);
        a98 = __ldg(w0 + (size_t)9 * Nsrc + c8);
    }
    uint4 o;
    o.x = pack_half2(a00, a10);
    o.y = pack_half2(a80, a90);
    o.z = pack_half2(a08, a18);
    o.w = pack_half2(a88, a98);
    out[g] = o;
}

// ---------------------------------------------------------------------------
// fp16 GEMM: 128x128 block, BK=64, 3 stages (96KB), 8 warps (2M x 4N),
// warp tile 64x32, 2 CTAs/SM.
// ---------------------------------------------------------------------------
#define STAGES 3
#define A_CH 1024      // uint4 per stage: 2 x (128r x 32k) A tiles
#define B_CH 1024      // uint4 per stage: 2 x (32k x 128n) B tiles
#define SMEM_BYTES (STAGES * (A_CH + B_CH) * 16)   // 96KB

__device__ __forceinline__ void mma16816(float* d, const uint4& a,
                                         uint32_t b0, uint32_t b1) {
    asm volatile(
        "mma.sync.aligned.m16n8k16.row.col.f32.f16.f16.f32 "
        "{%0,%1,%2,%3}, {%4,%5,%6,%7}, {%8,%9}, {%0,%1,%2,%3};\n"
        : "+f"(d[0]), "+f"(d[1]), "+f"(d[2]), "+f"(d[3])
        : "r"(a.x), "r"(a.y), "r"(a.z), "r"(a.w), "r"(b0), "r"(b1));
}

template <bool SIGMOID, bool PACKED_OUT>
__global__ void __launch_bounds__(256, 2)
gemm_fp16_kernel(const uint4* __restrict__ Apk,
                 const uint4* __restrict__ Bpk,
                 const float* __restrict__ bias,
                 void* __restrict__ outp,
                 int KTs, int KTout, int Nreal, int nTiles) {
    extern __shared__ uint4 sm4[];
    uint4* As = sm4;
    uint4* Bs = sm4 + STAGES * A_CH;

    const int tid = threadIdx.x;
    const int lane = tid & 31;
    const int warp = tid >> 5;
    const int wm = warp & 1, wn = warp >> 1;   // 2M x 4N, warp 64x32
    const int lr = lane >> 2, lc = lane & 3;

    const int GRP = 8;
    int per = GRP * nTiles;
    int mt = (blockIdx.x / per) * GRP + (blockIdx.x % per) % GRP;
    int nt = (blockIdx.x % per) / GRP;
    const int m0 = mt * 128, n0 = nt * 128;
    const int KT2c = KTs / 2;

    float acc[4][4][4];
#pragma unroll
    for (int i = 0; i < 4; i++)
#pragma unroll
        for (int j = 0; j < 4; j++)
#pragma unroll
            for (int k = 0; k < 4; k++) acc[i][j][k] = 0.f;

    auto load_stage = [&](int kt2, int s) {
        const uint4* ag = Apk + ((size_t)mt * KTs + kt2 * 2) * 512;
        uint4* as = As + s * A_CH;
#pragma unroll
        for (int p = 0; p < 4; p++) {
            int ci = tid + p * 256;
            cp_async16((uint32_t)__cvta_generic_to_shared(as + ci), ag + ci);
        }
        const uint4* bg = Bpk + ((size_t)nt * KTs + kt2 * 2) * 512;
        uint4* bs = Bs + s * B_CH;
#pragma unroll
        for (int p = 0; p < 4; p++) {
            int ci = tid + p * 256;
            cp_async16((uint32_t)__cvta_generic_to_shared(bs + ci), bg + ci);
        }
        asm volatile("cp.async.commit_group;\n");
    };

    load_stage(0, 0);
    load_stage(1, 1);

    int s = 0;
    for (int kt2 = 0; kt2 < KT2c; kt2++) {
        asm volatile("cp.async.wait_group 1;\n");
        __syncthreads();
        if (kt2 + 2 < KT2c) {
            int ns = s + 2; if (ns >= STAGES) ns -= STAGES;
            load_stage(kt2 + 2, ns);
        } else {
            asm volatile("cp.async.commit_group;\n");
        }

        const uint4* as = As + s * A_CH;
        const uint4* bs = Bs + s * B_CH;

#pragma unroll
        for (int ksg = 0; ksg < 4; ksg++) {
            const int half = ksg >> 1, ks = ksg & 1;
            uint4 av[4];
#pragma unroll
            for (int mf = 0; mf < 4; mf++)
                av[mf] = as[half * 512 + ks * 256 + (wm * 4 + mf) * 32 + lane];
            uint4 bv[2];
#pragma unroll
            for (int np = 0; np < 2; np++)
                bv[np] = bs[half * 512 + (ks * 8 + wn * 2 + np) * 32 + lane];
#pragma unroll
            for (int mf = 0; mf < 4; mf++)
#pragma unroll
                for (int np = 0; np < 2; np++) {
                    mma16816(acc[mf][2 * np],     av[mf], bv[np].x, bv[np].y);
                    mma16816(acc[mf][2 * np + 1], av[mf], bv[np].z, bv[np].w);
                }
        }
        if (++s == STAGES) s = 0;
        // next iteration's top barrier orders stage reuse
    }

    // ------------------ epilogue ------------------
#pragma unroll
    for (int mf = 0; mf < 4; mf++) {
        const int r0 = m0 + wm * 64 + mf * 16 + lr;
        const int grp = wm * 4 + mf;
#pragma unroll
        for (int npi = 0; npi < 2; npi++) {
            const int nf = npi * 2;
            const int c = n0 + wn * 32 + nf * 8 + lc * 2;
            float b0 = 0.f, b1 = 0.f, b2 = 0.f, b3 = 0.f;
            if (!PACKED_OUT) {
                if (c < Nreal)     b0 = __ldg(bias + c);
                if (c + 1 < Nreal) b1 = __ldg(bias + c + 1);
                if (c + 8 < Nreal) b2 = __ldg(bias + c + 8);
                if (c + 9 < Nreal) b3 = __ldg(bias + c + 9);
            } else {
                b0 = __ldg(bias + c);     b1 = __ldg(bias + c + 1);
                b2 = __ldg(bias + c + 8); b3 = __ldg(bias + c + 9);
            }
            float v00 = acc[mf][nf][0] + b0,     v01 = acc[mf][nf][1] + b1;
            float v10 = acc[mf][nf][2] + b0,     v11 = acc[mf][nf][3] + b1;
            float v20 = acc[mf][nf + 1][0] + b2, v21 = acc[mf][nf + 1][1] + b3;
            float v30 = acc[mf][nf + 1][2] + b2, v31 = acc[mf][nf + 1][3] + b3;
            if (SIGMOID) {
                v00 = 1.f / (1.f + __expf(-v00)); v01 = 1.f / (1.f + __expf(-v01));
                v10 = 1.f / (1.f + __expf(-v10)); v11 = 1.f / (1.f + __expf(-v11));
                v20 = 1.f / (1.f + __expf(-v20)); v21 = 1.f / (1.f + __expf(-v21));
                v30 = 1.f / (1.f + __expf(-v30)); v31 = 1.f / (1.f + __expf(-v31));
            }
            if (PACKED_OUT) {
                int kt2o = c >> 5;          // 32-k tile of downstream GEMM
                int ks2 = npi;              // k16 half within it
                size_t chunk = ((size_t)mt * KTout + kt2o) * 512
                             + ks2 * 256 + grp * 32 + lane;
                uint4 o;
                o.x = pack_half2(v00, v01);
                o.y = pack_half2(v10, v11);
                o.z = pack_half2(v20, v21);
                o.w = pack_half2(v30, v31);
                reinterpret_cast<uint4*>(outp)[chunk] = o;
            } else {
                float* C = reinterpret_cast<float*>(outp);
                if (c < Nreal)     C[(size_t)r0 * Nreal + c] = v00;
                if (c + 1 < Nreal) C[(size_t)r0 * Nreal + c + 1] = v01;
                if (c < Nreal)     C[(size_t)(r0 + 8) * Nreal + c] = v10;
                if (c + 1 < Nreal) C[(size_t)(r0 + 8) * Nreal + c + 1] = v11;
                if (c + 8 < Nreal) C[(size_t)r0 * Nreal + c + 8] = v20;
                if (c + 9 < Nreal) C[(size_t)r0 * Nreal + c + 9] = v21;
                if (c + 8 < Nreal) C[(size_t)(r0 + 8) * Nreal + c + 8] = v30;
                if (c + 9 < Nreal) C[(size_t)(r0 + 8) * Nreal + c + 9] = v31;
            }
        }
    }
}

// ---------------------------------------------------------------------------
// Launch
// ---------------------------------------------------------------------------
extern "C" void kernel_launch(void* const* d_in, const int* in_sizes, int n_in,
                              void* d_out, int out_size) {
    const float* x       = (const float*)d_in[0];
    const float* centers = (const float*)d_in[1];
    const float* scales  = (const float*)d_in[2];
    const float* Wb      = (const float*)d_in[3];
    const float* bb      = (const float*)d_in[4];
    const float* Wh      = (const float*)d_in[5];
    const float* bh      = (const float*)d_in[6];
    float* out = (float*)d_out;

    uint4 *F, *PHI, *WbP, *WhP;
    cudaGetSymbolAddress((void**)&F, g_F);
    cudaGetSymbolAddress((void**)&PHI, g_PHI);
    cudaGetSymbolAddress((void**)&WbP, g_WbP);
    cudaGetSymbolAddress((void**)&WhP, g_WhP);

    cudaFuncSetAttribute((const void*)gemm_fp16_kernel<true, true>,
                         cudaFuncAttributeMaxDynamicSharedMemorySize, SMEM_BYTES);
    cudaFuncSetAttribute((const void*)gemm_fp16_kernel<false, false>,
                         cudaFuncAttributeMaxDynamicSharedMemorySize, SMEM_BYTES);

    // 1) feats -> packed fp16 F
    {
        size_t chunks = (size_t)BATCH * KDIM / 8;
        feats_packed_kernel<<<(int)(chunks / 256), 256>>>(x, centers, scales, F);
    }
    // 2) pack Wb, Wh (128-wide n tiles)
    {
        size_t cb = (size_t)KDIM * HIDDEN / 8;
        convert_pack_b_kernel<<<(int)(cb / 256), 256>>>(Wb, WbP, KT1, HIDDEN);
        size_t ch = (size_t)HIDDEN * NPAD / 8;
        convert_pack_b_kernel<<<(int)(ch / 256), 256>>>(Wh, WhP, KT2, CLASSES);
    }
    // 3) GEMM1: PHI(packed) = sigmoid(F @ Wb + bb)
    {
        int nT = HIDDEN / 128;                 // 32
        int grid = (BATCH / 128) * nT;         // 1024
        gemm_fp16_kernel<true, true><<<grid, 256, SMEM_BYTES>>>(
            F, WbP, bb, PHI, KT1, KT2, HIDDEN, nT);
    }
    // 4) GEMM2: out = PHI @ Wh + bh
    {
        int nT = NPAD / 128;                   // 8
        int grid = (BATCH / 128) * nT;         // 256
        gemm_fp16_kernel<false, false><<<grid, 256, SMEM_BYTES>>>(
            PHI, WhP, bh, out, KT2, 0, CLASSES, nT);
    }
}